// round 4
// baseline (speedup 1.0000x reference)
#include <cuda_runtime.h>
#include <math.h>

#define CB   2048
#define CL   64
#define CIN  300
#define CM   150
#define CIOU 450
#define TREES (2*CB)

// Scratch: ping-pong h/c buffers (device globals — no allocation APIs).
__device__ float g_h0[TREES*CL*CM];
__device__ float g_c0[TREES*CL*CM];
__device__ float g_h1[TREES*(CL/2)*CM];
__device__ float g_c1[TREES*(CL/2)*CM];

__device__ __forceinline__ float fsig(float x) { return 1.0f / (1.0f + __expf(-x)); }
__device__ __forceinline__ float ftanh(float x) { return 2.0f * fsig(2.0f * x) - 1.0f; }

// ---------------------------------------------------------------------------
// Leaf kernel: rows = 2*B*L. Per row: x = emb[token]; iou = x@Wioux + bioux +
// biouh; c = sig(i)*tanh(u); h = sig(o)*tanh(c). Block = 16 rows, 128 threads,
// each thread owns 4 output columns (tid + 128j).
// ---------------------------------------------------------------------------
__global__ __launch_bounds__(128, 4) void leaf_kernel(
    const int* __restrict__ lt, const int* __restrict__ rt,
    const float* __restrict__ emb, const float* __restrict__ Wioux,
    const float* __restrict__ bioux, const float* __restrict__ biouh)
{
    __shared__ __align__(16) float sm[16 * 452];   // xs [16][304] then out [16][452]
    __shared__ int stok[16];
    const int tid = threadIdx.x;
    const int r0 = blockIdx.x << 4;

    if (tid < 16) {
        int r = r0 + tid;
        int side = r / (CB * CL);
        int idx = r - side * (CB * CL);
        stok[tid] = side ? rt[idx] : lt[idx];
    }
    __syncthreads();

    #pragma unroll
    for (int rr = 0; rr < 16; rr++) {
        const float* src = emb + (long)stok[rr] * CIN;
        for (int k = tid; k < CIN; k += 128)
            sm[rr * 304 + k] = src[k];
    }
    __syncthreads();

    float acc[16][4];
    #pragma unroll
    for (int rr = 0; rr < 16; rr++) {
        acc[rr][0] = 0.f; acc[rr][1] = 0.f; acc[rr][2] = 0.f; acc[rr][3] = 0.f;
    }

    int col[4]; bool cv[4];
    #pragma unroll
    for (int j = 0; j < 4; j++) {
        col[j] = tid + 128 * j;
        cv[j] = col[j] < CIOU;
        if (!cv[j]) col[j] = 0;
    }
    const float* wp0 = Wioux + col[0];
    const float* wp1 = Wioux + col[1];
    const float* wp2 = Wioux + col[2];
    const float* wp3 = Wioux + col[3];

    for (int k0 = 0; k0 < CIN; k0 += 4) {       // 300 divisible by 4
        float w[4][4];
        #pragma unroll
        for (int kk = 0; kk < 4; kk++) {
            int o = (k0 + kk) * CIOU;
            w[kk][0] = wp0[o]; w[kk][1] = wp1[o]; w[kk][2] = wp2[o]; w[kk][3] = wp3[o];
        }
        #pragma unroll
        for (int rr = 0; rr < 16; rr++) {
            float4 a4 = *(const float4*)(sm + rr * 304 + k0);
            float av[4] = {a4.x, a4.y, a4.z, a4.w};
            #pragma unroll
            for (int kk = 0; kk < 4; kk++)
                #pragma unroll
                for (int j = 0; j < 4; j++)
                    acc[rr][j] = fmaf(av[kk], w[kk][j], acc[rr][j]);
        }
    }
    __syncthreads();                            // done reading x tile

    #pragma unroll
    for (int j = 0; j < 4; j++) {
        if (!cv[j]) continue;
        float bias = bioux[col[j]] + biouh[col[j]];
        #pragma unroll
        for (int rr = 0; rr < 16; rr++)
            sm[rr * 452 + col[j]] = acc[rr][j] + bias;
    }
    __syncthreads();

    for (int idx = tid; idx < 16 * CM; idx += 128) {
        int rr = idx / CM, m = idx - rr * CM;
        const float* row = sm + rr * 452;
        float i = row[m], o = row[150 + m], u = row[300 + m];
        float c = fsig(i) * ftanh(u);
        float h = fsig(o) * ftanh(c);
        int off = (r0 + rr) * CM + m;
        g_h0[off] = h;
        g_c0[off] = c;
    }
}

// ---------------------------------------------------------------------------
// Tree level kernel. Block = 16 parent nodes, 128 threads.
// Smem row (width 760): hl [0:150), hr [152:302), hsum [304:454), f [456:756).
// Phase B: forget gates as 32 child-rows x 150 cols over Wfh.
// Phase A: iou = hsum @ Wiouh (450 cols). iou overwrites [0:450) after sync.
// Epilogue: c = sig(i)*tanh(u) + fl*cl + fr*cr; h = sig(o)*tanh(c).
// ---------------------------------------------------------------------------
__global__ __launch_bounds__(128, 4) void tree_kernel(int dir, int nChild,
    const float* __restrict__ Wiouh, const float* __restrict__ biouh,
    const float* __restrict__ Wfh, const float* __restrict__ bfh)
{
    const float* hIn; const float* cIn; float* hOut; float* cOut;
    if (dir == 0) { hIn = g_h0; cIn = g_c0; hOut = g_h1; cOut = g_c1; }
    else          { hIn = g_h1; cIn = g_c1; hOut = g_h0; cOut = g_c0; }

    __shared__ __align__(16) float sm[16 * 760];
    __shared__ int sbase[16];
    const int tid = threadIdx.x;
    const int node0 = blockIdx.x << 4;
    const int np = nChild >> 1;

    if (tid < 16) {
        int node = node0 + tid;
        int t = node / np, p = node - t * np;
        sbase[tid] = (t * nChild + 2 * p) * CM;
    }
    __syncthreads();

    #pragma unroll
    for (int rr = 0; rr < 16; rr++) {
        const float* src = hIn + sbase[rr];
        for (int k = tid; k < 2 * CM; k += 128) {
            int d = (k < CM) ? k : k + 2;       // hr starts at 152
            sm[rr * 760 + d] = src[k];
        }
    }
    __syncthreads();

    for (int idx = tid; idx < 16 * CM; idx += 128) {
        int rr = idx / CM, m = idx - rr * CM;
        sm[rr * 760 + 304 + m] = sm[rr * 760 + m] + sm[rr * 760 + 152 + m];
    }
    __syncthreads();

    // ---- Phase B: forget gates (32 child rows, cols tid and tid+128) ----
    {
        int c0 = tid, c1 = tid + 128;
        bool v1 = c1 < CM;                       // tid < 22
        const float* w0 = Wfh + c0;
        const float* w1 = Wfh + (v1 ? c1 : 0);
        float acc[32][2];
        #pragma unroll
        for (int r = 0; r < 32; r++) { acc[r][0] = 0.f; acc[r][1] = 0.f; }

        for (int k0 = 0; k0 < 148; k0 += 4) {
            float w[4][2];
            #pragma unroll
            for (int kk = 0; kk < 4; kk++) {
                int o = (k0 + kk) * CM;
                w[kk][0] = w0[o]; w[kk][1] = w1[o];
            }
            #pragma unroll
            for (int cr = 0; cr < 32; cr++) {
                float4 a4 = *(const float4*)(sm + (cr >> 1) * 760 + (cr & 1) * 152 + k0);
                float av[4] = {a4.x, a4.y, a4.z, a4.w};
                #pragma unroll
                for (int kk = 0; kk < 4; kk++) {
                    acc[cr][0] = fmaf(av[kk], w[kk][0], acc[cr][0]);
                    acc[cr][1] = fmaf(av[kk], w[kk][1], acc[cr][1]);
                }
            }
        }
        for (int k = 148; k < 150; k++) {        // K=150 tail
            float wA = w0[k * CM], wB = w1[k * CM];
            #pragma unroll
            for (int cr = 0; cr < 32; cr++) {
                float a = sm[(cr >> 1) * 760 + (cr & 1) * 152 + k];
                acc[cr][0] = fmaf(a, wA, acc[cr][0]);
                acc[cr][1] = fmaf(a, wB, acc[cr][1]);
            }
        }
        float b0 = bfh[c0];
        #pragma unroll
        for (int cr = 0; cr < 32; cr++)
            sm[(cr >> 1) * 760 + 456 + (cr & 1) * 150 + c0] = acc[cr][0] + b0;
        if (v1) {
            float b1 = bfh[c1];
            #pragma unroll
            for (int cr = 0; cr < 32; cr++)
                sm[(cr >> 1) * 760 + 456 + (cr & 1) * 150 + c1] = acc[cr][1] + b1;
        }
    }

    // ---- Phase A: iou over hsum (450 cols) ----
    {
        int col[4]; bool cv[4];
        #pragma unroll
        for (int j = 0; j < 4; j++) {
            col[j] = tid + 128 * j;
            cv[j] = col[j] < CIOU;
            if (!cv[j]) col[j] = 0;
        }
        const float* wp0 = Wiouh + col[0];
        const float* wp1 = Wiouh + col[1];
        const float* wp2 = Wiouh + col[2];
        const float* wp3 = Wiouh + col[3];

        float acc[16][4];
        #pragma unroll
        for (int rr = 0; rr < 16; rr++) {
            acc[rr][0] = 0.f; acc[rr][1] = 0.f; acc[rr][2] = 0.f; acc[rr][3] = 0.f;
        }

        for (int k0 = 0; k0 < 148; k0 += 4) {
            float w[4][4];
            #pragma unroll
            for (int kk = 0; kk < 4; kk++) {
                int o = (k0 + kk) * CIOU;
                w[kk][0] = wp0[o]; w[kk][1] = wp1[o]; w[kk][2] = wp2[o]; w[kk][3] = wp3[o];
            }
            #pragma unroll
            for (int rr = 0; rr < 16; rr++) {
                float4 a4 = *(const float4*)(sm + rr * 760 + 304 + k0);
                float av[4] = {a4.x, a4.y, a4.z, a4.w};
                #pragma unroll
                for (int kk = 0; kk < 4; kk++)
                    #pragma unroll
                    for (int j = 0; j < 4; j++)
                        acc[rr][j] = fmaf(av[kk], w[kk][j], acc[rr][j]);
            }
        }
        for (int k = 148; k < 150; k++) {
            float w[4];
            w[0] = wp0[k * CIOU]; w[1] = wp1[k * CIOU];
            w[2] = wp2[k * CIOU]; w[3] = wp3[k * CIOU];
            #pragma unroll
            for (int rr = 0; rr < 16; rr++) {
                float a = sm[rr * 760 + 304 + k];
                #pragma unroll
                for (int j = 0; j < 4; j++)
                    acc[rr][j] = fmaf(a, w[j], acc[rr][j]);
            }
        }

        __syncthreads();      // all reads of hl/hr/hsum complete (phases A+B done)

        #pragma unroll
        for (int j = 0; j < 4; j++) {
            if (!cv[j]) continue;
            float bias = biouh[col[j]];
            #pragma unroll
            for (int rr = 0; rr < 16; rr++)
                sm[rr * 760 + col[j]] = acc[rr][j] + bias;   // iou overwrites input
        }
    }
    __syncthreads();

    // ---- Epilogue ----
    for (int idx = tid; idx < 16 * CM; idx += 128) {
        int rr = idx / CM, m = idx - rr * CM;
        const float* row = sm + rr * 760;
        float i = row[m], o = row[150 + m], u = row[300 + m];
        float fl = fsig(row[456 + m]);
        float fr = fsig(row[606 + m]);
        int base = sbase[rr];
        float clv = cIn[base + m];
        float crv = cIn[base + CM + m];
        float c = fsig(i) * ftanh(u) + fl * clv + fr * crv;
        float h = fsig(o) * ftanh(c);
        int off = (node0 + rr) * CM + m;
        hOut[off] = h;
        cOut[off] = c;
    }
}

// ---------------------------------------------------------------------------
// Final head: one block per sentence pair.
// ---------------------------------------------------------------------------
__global__ void final_kernel(
    const float* __restrict__ Wh, const float* __restrict__ bh,
    const float* __restrict__ Wp, const float* __restrict__ bp,
    float* __restrict__ out)
{
    __shared__ float vec[2 * CM];
    __shared__ float mid[50];
    __shared__ float pv[6];
    int b = blockIdx.x, tid = threadIdx.x;

    for (int m = tid; m < CM; m += 64) {
        float lh = g_h0[b * CM + m];
        float rh = g_h0[(CB + b) * CM + m];
        vec[m] = lh * rh;
        vec[CM + m] = fabsf(lh - rh);
    }
    __syncthreads();

    if (tid < 50) {
        float a = bh[tid];
        for (int k = 0; k < 2 * CM; k++)
            a = fmaf(vec[k], Wh[k * 50 + tid], a);
        mid[tid] = fsig(a);
    }
    __syncthreads();

    if (tid < 5) {
        float a = bp[tid];
        for (int k = 0; k < 50; k++)
            a = fmaf(mid[k], Wp[k * 5 + tid], a);
        pv[tid] = a;
    }
    __syncthreads();

    if (tid == 0) {
        float mx = pv[0];
        for (int c = 1; c < 5; c++) mx = fmaxf(mx, pv[c]);
        float s = 0.f;
        for (int c = 0; c < 5; c++) s += expf(pv[c] - mx);
        pv[5] = mx + logf(s);
    }
    __syncthreads();

    if (tid < 5) out[b * 5 + tid] = pv[tid] - pv[5];
}

// ---------------------------------------------------------------------------
extern "C" void kernel_launch(void* const* d_in, const int* in_sizes, int n_in,
                              void* d_out, int out_size)
{
    (void)in_sizes; (void)n_in; (void)out_size;
    const int*   lt    = (const int*)d_in[0];
    const int*   rt    = (const int*)d_in[1];
    const float* emb   = (const float*)d_in[2];
    const float* Wioux = (const float*)d_in[3];
    const float* bioux = (const float*)d_in[4];
    const float* Wiouh = (const float*)d_in[5];
    const float* biouh = (const float*)d_in[6];
    // d_in[7] = Wfx, d_in[8] = bfx: unused by the reference computation
    const float* Wfh   = (const float*)d_in[9];
    const float* bfh   = (const float*)d_in[10];
    const float* Wh    = (const float*)d_in[11];
    const float* bh    = (const float*)d_in[12];
    const float* Wp    = (const float*)d_in[13];
    const float* bp    = (const float*)d_in[14];
    float* out = (float*)d_out;

    leaf_kernel<<<TREES * CL / 16, 128>>>(lt, rt, emb, Wioux, bioux, biouh);

    int dir = 0;
    for (int n = CL; n > 1; n >>= 1) {
        int blocks = TREES * (n / 2) / 16;
        tree_kernel<<<blocks, 128>>>(dir, n, Wiouh, biouh, Wfh, bfh);
        dir ^= 1;
    }
    // After 6 levels (64->32->16->8->4->2->1) the roots land in g_h0.

    final_kernel<<<CB, 64>>>(Wh, bh, Wp, bp, out);
}

// round 5
// speedup vs baseline: 1.0012x; 1.0012x over previous
#include <cuda_runtime.h>
#include <math.h>

#define CB   2048
#define CL   64
#define CIN  300
#define CM   150
#define CIOU 450
#define TREES (2*CB)

// Scratch: ping-pong h/c buffers (device globals — no allocation APIs).
__device__ float g_h0[TREES*CL*CM];
__device__ float g_c0[TREES*CL*CM];
__device__ float g_h1[TREES*(CL/2)*CM];
__device__ float g_c1[TREES*(CL/2)*CM];

__device__ __forceinline__ float fsig(float x) { return 1.0f / (1.0f + __expf(-x)); }
__device__ __forceinline__ float ftanh(float x) { return 2.0f * fsig(2.0f * x) - 1.0f; }

// ---------------------------------------------------------------------------
// Leaf kernel: rows = 2*B*L. Per row: x = emb[token]; iou = x@Wioux + bioux +
// biouh; c = sig(i)*tanh(u); h = sig(o)*tanh(c). Block = 16 rows, 128 threads,
// each thread owns 4 output columns (tid + 128j).
// ---------------------------------------------------------------------------
__global__ __launch_bounds__(128, 4) void leaf_kernel(
    const int* __restrict__ lt, const int* __restrict__ rt,
    const float* __restrict__ emb, const float* __restrict__ Wioux,
    const float* __restrict__ bioux, const float* __restrict__ biouh)
{
    __shared__ __align__(16) float sm[16 * 452];   // xs [16][304] then out [16][452]
    __shared__ int stok[16];
    const int tid = threadIdx.x;
    const int r0 = blockIdx.x << 4;

    if (tid < 16) {
        int r = r0 + tid;
        int side = r / (CB * CL);
        int idx = r - side * (CB * CL);
        stok[tid] = side ? rt[idx] : lt[idx];
    }
    __syncthreads();

    #pragma unroll
    for (int rr = 0; rr < 16; rr++) {
        const float* src = emb + (long)stok[rr] * CIN;
        for (int k = tid; k < CIN; k += 128)
            sm[rr * 304 + k] = src[k];
    }
    __syncthreads();

    float acc[16][4];
    #pragma unroll
    for (int rr = 0; rr < 16; rr++) {
        acc[rr][0] = 0.f; acc[rr][1] = 0.f; acc[rr][2] = 0.f; acc[rr][3] = 0.f;
    }

    int col[4]; bool cv[4];
    #pragma unroll
    for (int j = 0; j < 4; j++) {
        col[j] = tid + 128 * j;
        cv[j] = col[j] < CIOU;
        if (!cv[j]) col[j] = 0;
    }
    const float* wp0 = Wioux + col[0];
    const float* wp1 = Wioux + col[1];
    const float* wp2 = Wioux + col[2];
    const float* wp3 = Wioux + col[3];

    for (int k0 = 0; k0 < CIN; k0 += 4) {       // 300 divisible by 4
        float w[4][4];
        #pragma unroll
        for (int kk = 0; kk < 4; kk++) {
            int o = (k0 + kk) * CIOU;
            w[kk][0] = wp0[o]; w[kk][1] = wp1[o]; w[kk][2] = wp2[o]; w[kk][3] = wp3[o];
        }
        #pragma unroll
        for (int rr = 0; rr < 16; rr++) {
            float4 a4 = *(const float4*)(sm + rr * 304 + k0);
            float av[4] = {a4.x, a4.y, a4.z, a4.w};
            #pragma unroll
            for (int kk = 0; kk < 4; kk++)
                #pragma unroll
                for (int j = 0; j < 4; j++)
                    acc[rr][j] = fmaf(av[kk], w[kk][j], acc[rr][j]);
        }
    }
    __syncthreads();                            // done reading x tile

    #pragma unroll
    for (int j = 0; j < 4; j++) {
        if (!cv[j]) continue;
        float bias = bioux[col[j]] + biouh[col[j]];
        #pragma unroll
        for (int rr = 0; rr < 16; rr++)
            sm[rr * 452 + col[j]] = acc[rr][j] + bias;
    }
    __syncthreads();

    for (int idx = tid; idx < 16 * CM; idx += 128) {
        int rr = idx / CM, m = idx - rr * CM;
        const float* row = sm + rr * 452;
        float i = row[m], o = row[150 + m], u = row[300 + m];
        float c = fsig(i) * ftanh(u);
        float h = fsig(o) * ftanh(c);
        int off = (r0 + rr) * CM + m;
        g_h0[off] = h;
        g_c0[off] = c;
    }
}

// ---------------------------------------------------------------------------
// Tree level kernel. Block = 16 parent nodes, 128 threads.
// Smem row (width 760): hl [0:150), hr [152:302), hsum [304:454), f [456:756).
// Phase B: forget gates as 32 child-rows x 150 cols over Wfh.
// Phase A: iou = hsum @ Wiouh (450 cols). iou overwrites [0:450) after sync.
// Epilogue: c = sig(i)*tanh(u) + fl*cl + fr*cr; h = sig(o)*tanh(c).
// ---------------------------------------------------------------------------
__global__ __launch_bounds__(128, 4) void tree_kernel(int dir, int nChild,
    const float* __restrict__ Wiouh, const float* __restrict__ biouh,
    const float* __restrict__ Wfh, const float* __restrict__ bfh)
{
    const float* hIn; const float* cIn; float* hOut; float* cOut;
    if (dir == 0) { hIn = g_h0; cIn = g_c0; hOut = g_h1; cOut = g_c1; }
    else          { hIn = g_h1; cIn = g_c1; hOut = g_h0; cOut = g_c0; }

    __shared__ __align__(16) float sm[16 * 760];
    __shared__ int sbase[16];
    const int tid = threadIdx.x;
    const int node0 = blockIdx.x << 4;
    const int np = nChild >> 1;

    if (tid < 16) {
        int node = node0 + tid;
        int t = node / np, p = node - t * np;
        sbase[tid] = (t * nChild + 2 * p) * CM;
    }
    __syncthreads();

    #pragma unroll
    for (int rr = 0; rr < 16; rr++) {
        const float* src = hIn + sbase[rr];
        for (int k = tid; k < 2 * CM; k += 128) {
            int d = (k < CM) ? k : k + 2;       // hr starts at 152
            sm[rr * 760 + d] = src[k];
        }
    }
    __syncthreads();

    for (int idx = tid; idx < 16 * CM; idx += 128) {
        int rr = idx / CM, m = idx - rr * CM;
        sm[rr * 760 + 304 + m] = sm[rr * 760 + m] + sm[rr * 760 + 152 + m];
    }
    __syncthreads();

    // ---- Phase B: forget gates (32 child rows, cols tid and tid+128) ----
    {
        int c0 = tid, c1 = tid + 128;
        bool v1 = c1 < CM;                       // tid < 22
        const float* w0 = Wfh + c0;
        const float* w1 = Wfh + (v1 ? c1 : 0);
        float acc[32][2];
        #pragma unroll
        for (int r = 0; r < 32; r++) { acc[r][0] = 0.f; acc[r][1] = 0.f; }

        for (int k0 = 0; k0 < 148; k0 += 4) {
            float w[4][2];
            #pragma unroll
            for (int kk = 0; kk < 4; kk++) {
                int o = (k0 + kk) * CM;
                w[kk][0] = w0[o]; w[kk][1] = w1[o];
            }
            #pragma unroll
            for (int cr = 0; cr < 32; cr++) {
                float4 a4 = *(const float4*)(sm + (cr >> 1) * 760 + (cr & 1) * 152 + k0);
                float av[4] = {a4.x, a4.y, a4.z, a4.w};
                #pragma unroll
                for (int kk = 0; kk < 4; kk++) {
                    acc[cr][0] = fmaf(av[kk], w[kk][0], acc[cr][0]);
                    acc[cr][1] = fmaf(av[kk], w[kk][1], acc[cr][1]);
                }
            }
        }
        for (int k = 148; k < 150; k++) {        // K=150 tail
            float wA = w0[k * CM], wB = w1[k * CM];
            #pragma unroll
            for (int cr = 0; cr < 32; cr++) {
                float a = sm[(cr >> 1) * 760 + (cr & 1) * 152 + k];
                acc[cr][0] = fmaf(a, wA, acc[cr][0]);
                acc[cr][1] = fmaf(a, wB, acc[cr][1]);
            }
        }
        float b0 = bfh[c0];
        #pragma unroll
        for (int cr = 0; cr < 32; cr++)
            sm[(cr >> 1) * 760 + 456 + (cr & 1) * 150 + c0] = acc[cr][0] + b0;
        if (v1) {
            float b1 = bfh[c1];
            #pragma unroll
            for (int cr = 0; cr < 32; cr++)
                sm[(cr >> 1) * 760 + 456 + (cr & 1) * 150 + c1] = acc[cr][1] + b1;
        }
    }

    // ---- Phase A: iou over hsum (450 cols) ----
    {
        int col[4]; bool cv[4];
        #pragma unroll
        for (int j = 0; j < 4; j++) {
            col[j] = tid + 128 * j;
            cv[j] = col[j] < CIOU;
            if (!cv[j]) col[j] = 0;
        }
        const float* wp0 = Wiouh + col[0];
        const float* wp1 = Wiouh + col[1];
        const float* wp2 = Wiouh + col[2];
        const float* wp3 = Wiouh + col[3];

        float acc[16][4];
        #pragma unroll
        for (int rr = 0; rr < 16; rr++) {
            acc[rr][0] = 0.f; acc[rr][1] = 0.f; acc[rr][2] = 0.f; acc[rr][3] = 0.f;
        }

        for (int k0 = 0; k0 < 148; k0 += 4) {
            float w[4][4];
            #pragma unroll
            for (int kk = 0; kk < 4; kk++) {
                int o = (k0 + kk) * CIOU;
                w[kk][0] = wp0[o]; w[kk][1] = wp1[o]; w[kk][2] = wp2[o]; w[kk][3] = wp3[o];
            }
            #pragma unroll
            for (int rr = 0; rr < 16; rr++) {
                float4 a4 = *(const float4*)(sm + rr * 760 + 304 + k0);
                float av[4] = {a4.x, a4.y, a4.z, a4.w};
                #pragma unroll
                for (int kk = 0; kk < 4; kk++)
                    #pragma unroll
                    for (int j = 0; j < 4; j++)
                        acc[rr][j] = fmaf(av[kk], w[kk][j], acc[rr][j]);
            }
        }
        for (int k = 148; k < 150; k++) {
            float w[4];
            w[0] = wp0[k * CIOU]; w[1] = wp1[k * CIOU];
            w[2] = wp2[k * CIOU]; w[3] = wp3[k * CIOU];
            #pragma unroll
            for (int rr = 0; rr < 16; rr++) {
                float a = sm[rr * 760 + 304 + k];
                #pragma unroll
                for (int j = 0; j < 4; j++)
                    acc[rr][j] = fmaf(a, w[j], acc[rr][j]);
            }
        }

        __syncthreads();      // all reads of hl/hr/hsum complete (phases A+B done)

        #pragma unroll
        for (int j = 0; j < 4; j++) {
            if (!cv[j]) continue;
            float bias = biouh[col[j]];
            #pragma unroll
            for (int rr = 0; rr < 16; rr++)
                sm[rr * 760 + col[j]] = acc[rr][j] + bias;   // iou overwrites input
        }
    }
    __syncthreads();

    // ---- Epilogue ----
    for (int idx = tid; idx < 16 * CM; idx += 128) {
        int rr = idx / CM, m = idx - rr * CM;
        const float* row = sm + rr * 760;
        float i = row[m], o = row[150 + m], u = row[300 + m];
        float fl = fsig(row[456 + m]);
        float fr = fsig(row[606 + m]);
        int base = sbase[rr];
        float clv = cIn[base + m];
        float crv = cIn[base + CM + m];
        float c = fsig(i) * ftanh(u) + fl * clv + fr * crv;
        float h = fsig(o) * ftanh(c);
        int off = (node0 + rr) * CM + m;
        hOut[off] = h;
        cOut[off] = c;
    }
}

// ---------------------------------------------------------------------------
// Final head: one block per sentence pair.
// ---------------------------------------------------------------------------
__global__ void final_kernel(
    const float* __restrict__ Wh, const float* __restrict__ bh,
    const float* __restrict__ Wp, const float* __restrict__ bp,
    float* __restrict__ out)
{
    __shared__ float vec[2 * CM];
    __shared__ float mid[50];
    __shared__ float pv[6];
    int b = blockIdx.x, tid = threadIdx.x;

    for (int m = tid; m < CM; m += 64) {
        float lh = g_h0[b * CM + m];
        float rh = g_h0[(CB + b) * CM + m];
        vec[m] = lh * rh;
        vec[CM + m] = fabsf(lh - rh);
    }
    __syncthreads();

    if (tid < 50) {
        float a = bh[tid];
        for (int k = 0; k < 2 * CM; k++)
            a = fmaf(vec[k], Wh[k * 50 + tid], a);
        mid[tid] = fsig(a);
    }
    __syncthreads();

    if (tid < 5) {
        float a = bp[tid];
        for (int k = 0; k < 50; k++)
            a = fmaf(mid[k], Wp[k * 5 + tid], a);
        pv[tid] = a;
    }
    __syncthreads();

    if (tid == 0) {
        float mx = pv[0];
        for (int c = 1; c < 5; c++) mx = fmaxf(mx, pv[c]);
        float s = 0.f;
        for (int c = 0; c < 5; c++) s += expf(pv[c] - mx);
        pv[5] = mx + logf(s);
    }
    __syncthreads();

    if (tid < 5) out[b * 5 + tid] = pv[tid] - pv[5];
}

// ---------------------------------------------------------------------------
extern "C" void kernel_launch(void* const* d_in, const int* in_sizes, int n_in,
                              void* d_out, int out_size)
{
    (void)in_sizes; (void)n_in; (void)out_size;
    const int*   lt    = (const int*)d_in[0];
    const int*   rt    = (const int*)d_in[1];
    const float* emb   = (const float*)d_in[2];
    const float* Wioux = (const float*)d_in[3];
    const float* bioux = (const float*)d_in[4];
    const float* Wiouh = (const float*)d_in[5];
    const float* biouh = (const float*)d_in[6];
    // d_in[7] = Wfx, d_in[8] = bfx: unused by the reference computation
    const float* Wfh   = (const float*)d_in[9];
    const float* bfh   = (const float*)d_in[10];
    const float* Wh    = (const float*)d_in[11];
    const float* bh    = (const float*)d_in[12];
    const float* Wp    = (const float*)d_in[13];
    const float* bp    = (const float*)d_in[14];
    float* out = (float*)d_out;

    leaf_kernel<<<TREES * CL / 16, 128>>>(lt, rt, emb, Wioux, bioux, biouh);

    int dir = 0;
    for (int n = CL; n > 1; n >>= 1) {
        int blocks = TREES * (n / 2) / 16;
        tree_kernel<<<blocks, 128>>>(dir, n, Wiouh, biouh, Wfh, bfh);
        dir ^= 1;
    }
    // After 6 levels (64->32->16->8->4->2->1) the roots land in g_h0.

    final_kernel<<<CB, 64>>>(Wh, bh, Wp, bp, out);
}